// round 16
// baseline (speedup 1.0000x reference)
#include <cuda_runtime.h>
#include <cuda_fp16.h>
#include <math.h>
#include <stdint.h>

// Problem constants
#define B_  2
#define L_  256
#define C_  256
#define NTOK (B_*L_*L_)
#define LN_EPS 1e-5f
#define TM 64            // tokens per CTA (2 CTAs/SM)

// ---------------------------------------------------------------------------
// Device scratch (no cudaMalloc allowed)
__device__ __align__(16) float g_mod[B_][3*C_];
// W1 fp16, SW128: stage s=nc*4+kt -> 16KB [128n x 64k]
__device__ __align__(16) unsigned char g_w1[524288];
// W2 fp16, SW128: stage s=nc*2+kt -> 32KB [256c x 64k]
__device__ __align__(16) unsigned char g_w2[524288];

#define SWZ(o) ((o) ^ (((o)>>3)&0x70))

// ---------------------------------------------------------------------------
__device__ __forceinline__ uint32_t smem_u32(const void* p){
    uint32_t a;
    asm("{ .reg .u64 t; cvta.to.shared.u64 t, %1; cvt.u32.u64 %0, t; }"
        : "=r"(a) : "l"(p));
    return a;
}
#define MBAR_INIT(a,c) \
    asm volatile("mbarrier.init.shared.b64 [%0], %1;" :: "r"(a), "r"(c) : "memory")
#define MBAR_INVAL(a) \
    asm volatile("mbarrier.inval.shared.b64 [%0];" :: "r"(a) : "memory")
#define MBAR_EXPECT(a,tx) \
    asm volatile("mbarrier.arrive.expect_tx.shared.b64 _, [%0], %1;" :: "r"(a), "r"(tx) : "memory")
#define MBAR_ARRIVE(a) \
    asm volatile("mbarrier.arrive.shared.b64 _, [%0];" :: "r"(a) : "memory")
#define MBAR_WAIT(mb, ph) do{                                                   \
    uint32_t _m=(mb), _p=(ph), _d;                                              \
    asm volatile("{\n\t.reg .pred p;\n\t"                                       \
      "mbarrier.try_wait.parity.acquire.cta.shared::cta.b64 p, [%1], %2;\n\t"   \
      "selp.b32 %0,1,0,p;\n\t}" : "=r"(_d) : "r"(_m), "r"(_p) : "memory");      \
    while(!_d){                                                                 \
      asm volatile("{\n\t.reg .pred p;\n\t"                                     \
        "mbarrier.try_wait.parity.acquire.cta.shared::cta.b64 p, [%1], %2, 0x989680;\n\t" \
        "selp.b32 %0,1,0,p;\n\t}" : "=r"(_d) : "r"(_m), "r"(_p) : "memory"); }  \
}while(0)
#define BARH(id) asm volatile("bar.sync %0, 128;" :: "r"(id) : "memory")

__device__ __forceinline__ void bulk_g2s(uint32_t dst, const void* src,
                                         uint32_t bytes, uint32_t mbar){
    asm volatile("cp.async.bulk.shared::cluster.global.mbarrier::complete_tx::bytes "
                 "[%0], [%1], %2, [%3];"
                 :: "r"(dst), "l"(src), "r"(bytes), "r"(mbar) : "memory");
}

__device__ __forceinline__ void ldsm4(uint32_t* r, uint32_t a){
    asm volatile("ldmatrix.sync.aligned.m8n8.x4.shared.b16 {%0,%1,%2,%3}, [%4];"
        : "=r"(r[0]),"=r"(r[1]),"=r"(r[2]),"=r"(r[3]) : "r"(a));
}
__device__ __forceinline__ void mma_f16(float* c, const uint32_t* a, const uint32_t* b){
    asm volatile("mma.sync.aligned.m16n8k16.row.col.f32.f16.f16.f32 "
        "{%0,%1,%2,%3}, {%4,%5,%6,%7}, {%8,%9}, {%0,%1,%2,%3};"
        : "+f"(c[0]),"+f"(c[1]),"+f"(c[2]),"+f"(c[3])
        : "r"(a[0]),"r"(a[1]),"r"(a[2]),"r"(a[3]), "r"(b[0]),"r"(b[1]));
}

__device__ __forceinline__ float gelu_exact(float x){
    return 0.5f * x * (1.0f + erff(x * 0.70710678118654752440f));
}

// ---------------------------------------------------------------------------
// Weight prep: fp32 -> fp16, SW128 K-major tiles
__global__ void prep_w1(const float* __restrict__ w1){
    int n = blockIdx.x;            // 0..1023
    int k = threadIdx.x;           // 0..255
    float v = w1[n*256 + k];
    __half h = __float2half_rn(v);
    int nc = n >> 7, nl = n & 127, kt = k >> 6, kk = k & 63;
    size_t tbase = (size_t)(nc*4 + kt) * 16384u;
    uint32_t off = SWZ((uint32_t)(nl*128 + kk*2));
    *(__half*)(g_w1 + tbase + off) = h;
}
__global__ void prep_w2(const float* __restrict__ w2){
    int c = blockIdx.x;            // 0..255
    #pragma unroll
    for (int q = 0; q < 4; ++q){
        int k = threadIdx.x + q*256;   // 0..1023
        float v = w2[c*1024 + k];
        __half h = __float2half_rn(v);
        int nc = k >> 7, kt = (k >> 6) & 1, kk = k & 63;
        size_t tbase = (size_t)(nc*2 + kt) * 32768u;
        uint32_t off = SWZ((uint32_t)(c*128 + kk*2));
        *(__half*)(g_w2 + tbase + off) = h;
    }
}

// ---------------------------------------------------------------------------
// adaLN modulation
__global__ void mod_kernel(const float* __restrict__ c_BD,
                           const float* __restrict__ ada_w,
                           const float* __restrict__ ada_b){
    __shared__ float sc[C_];
    int b   = blockIdx.x / 12;
    int grp = blockIdx.x % 12;
    int tid = threadIdx.x;
    float cv = c_BD[b*C_ + tid];
    sc[tid] = cv / (1.0f + expf(-cv));
    __syncthreads();
    int oo = grp*64 + (tid >> 2);
    int k0 = (tid & 3) * 64;
    const float* wr = ada_w + oo*C_ + k0;
    const float* ss = sc + k0;
    float s = 0.0f;
    #pragma unroll 8
    for (int k = 0; k < 64; ++k) s = fmaf(ss[k], wr[k], s);
    s += __shfl_xor_sync(0xffffffffu, s, 1);
    s += __shfl_xor_sync(0xffffffffu, s, 2);
    if ((tid & 3) == 0) g_mod[b][oo] = s + ada_b[oo];
}

// ---------------------------------------------------------------------------
// SMEM layout (bytes) -- sized for 2 CTAs/SM (<= 116736 each)
#define OFF_A    0u         // A fp16 [64m x 512B]   (32KB)
#define OFF_W1   32768u     // 2 x 16KB ring         (32KB)
#define OFF_H1   65536u     // H1 fp16 [64m x 256B]  (16KB)
#define OFF_W2   81920u     // 1 x 32KB buffer       (32KB)
#define OFF_IDX  114688u    // int[64]
#define OFF_MB   114944u    // 6 mbarriers
#define SMEM_BYTES 115008u

#define FW1(buf) (sb + OFF_MB +  0u + (uint32_t)(buf)*8u)   // 2 bufs
#define EW1(buf) (sb + OFF_MB + 16u + (uint32_t)(buf)*8u)   // 2 bufs
#define FW2_     (sb + OFF_MB + 32u)
#define EW2_     (sb + OFF_MB + 40u)
#define W1BUF(buf) (sb + OFF_W1 + (uint32_t)(buf)*16384u)
#define W2BUF_     (sb + OFF_W2)

__global__ __launch_bounds__(256, 2)
void main_kernel(const float* __restrict__ x,
                 const float* __restrict__ bins,
                 const float* __restrict__ emb,
                 const float* __restrict__ pos,
                 const float* __restrict__ lng,
                 const float* __restrict__ lnb,
                 const float* __restrict__ b1,
                 const float* __restrict__ b2,
                 float* __restrict__ out){
    extern __shared__ __align__(1024) unsigned char smp[];
    const uint32_t sb = smem_u32(smp);
    const int tid  = threadIdx.x;
    const int warp = tid >> 5;
    const int lane = tid & 31;
    const int g    = lane >> 2;
    const int tg   = lane & 3;
    const int wm   = warp >> 2;       // 2 m-groups x 32 rows (span SMSPs)
    const int wn   = warp & 3;        // 4 n-groups

    const int t0 = blockIdx.x * TM;
    const int b  = t0 >> 16;
    const int ii = (t0 >> 8) & 255;
    const int j0 = t0 & 255;

    int* idxs = (int*)(smp + OFF_IDX);

    if (tid == 0){
        MBAR_INIT(FW1(0), 1); MBAR_INIT(FW1(1), 1);
        MBAR_INIT(EW1(0), 8); MBAR_INIT(EW1(1), 8);
        MBAR_INIT(FW2_, 1);   MBAR_INIT(EW2_, 8);
    }
    __syncthreads();
    if (tid == 0){
        MBAR_EXPECT(FW1(0), 16384u); bulk_g2s(W1BUF(0), g_w1,          16384u, FW1(0));
        MBAR_EXPECT(FW1(1), 16384u); bulk_g2s(W1BUF(1), g_w1 + 16384u, 16384u, FW1(1));
        MBAR_EXPECT(FW2_,   32768u); bulk_g2s(W2BUF_,   g_w2,          32768u, FW2_);
    }

    // distance buckets for this tile's 64 tokens
    if (tid < TM){
        int j = j0 + tid;
        const float* xi = x + (b*L_ + ii)*3;
        const float* xj = x + (b*L_ + j )*3;
        float d0 = __fadd_rn(xi[0], -xj[0]);
        float d1 = __fadd_rn(xi[1], -xj[1]);
        float d2v = __fadd_rn(xi[2], -xj[2]);
        float d  = __fadd_rn(__fadd_rn(__fmul_rn(d0,d0), __fmul_rn(d1,d1)),
                             __fmul_rn(d2v,d2v));
        int cnt = 0;
        #pragma unroll
        for (int k = 0; k < 63; ++k) cnt += (bins[k] < d) ? 1 : 0;
        idxs[tid] = cnt;
    }
    __syncthreads();

    // ---- Phase 0: s -> modulate -> LN -> fp16 into A ---------------------
    {
        float2 sh2[4], sc2[4], lg2[4], lb2[4];
        #pragma unroll
        for (int q = 0; q < 4; ++q){
            int c0 = 2*lane + 64*q;
            sh2[q] = *(const float2*)(&g_mod[b][c0]);
            sc2[q] = *(const float2*)(&g_mod[b][C_ + c0]);
            lg2[q] = *(const float2*)(lng + c0);
            lb2[q] = *(const float2*)(lnb + c0);
        }
        for (int r = 0; r < 8; ++r){
            int m = warp*8 + r;
            int idv = idxs[m];
            int rel = ii - (j0 + m);
            rel = rel < -64 ? -64 : (rel > 63 ? 63 : rel);
            rel += 64;
            const float2* er = (const float2*)(emb + (idv << 8));
            const float2* pr = (const float2*)(pos + (rel << 8));
            float vx[4], vy[4];
            float sum = 0.0f;
            #pragma unroll
            for (int q = 0; q < 4; ++q){
                int c0 = 2*lane + 64*q;
                float2 e = er[c0 >> 1];
                float2 p = pr[c0 >> 1];
                float a0 = fmaf(e.x + p.x, 1.0f + sc2[q].x, sh2[q].x);
                float a1 = fmaf(e.y + p.y, 1.0f + sc2[q].y, sh2[q].y);
                vx[q] = a0; vy[q] = a1;
                sum += a0 + a1;
            }
            #pragma unroll
            for (int off = 16; off; off >>= 1)
                sum += __shfl_xor_sync(0xffffffffu, sum, off);
            float mu = sum * (1.0f/256.0f);
            float sq = 0.0f;
            #pragma unroll
            for (int q = 0; q < 4; ++q){
                float a0 = vx[q]-mu, a1 = vy[q]-mu;
                sq = fmaf(a0,a0, fmaf(a1,a1, sq));
            }
            #pragma unroll
            for (int off = 16; off; off >>= 1)
                sq += __shfl_xor_sync(0xffffffffu, sq, off);
            float rstd = rsqrtf(sq * (1.0f/256.0f) + LN_EPS);
            uint32_t arow = (uint32_t)(m*512) + ((uint32_t)(4*lane) ^ (uint32_t)((m&7)<<4));
            #pragma unroll
            for (int q = 0; q < 4; ++q){
                float h0 = fmaf((vx[q]-mu)*rstd, lg2[q].x, lb2[q].x);
                float h1 = fmaf((vy[q]-mu)*rstd, lg2[q].y, lb2[q].y);
                __half2 hp = __floats2half2_rn(h0, h1);
                *(__half2*)(smp + OFF_A + arow + 128u*q) = hp;
            }
        }
    }
    __syncthreads();

    // per-warp LDSM address bases (hoisted)
    const uint32_t aBase0 = sb + OFF_A + (uint32_t)((wm*32 +  0 + (lane&15))*512);
    const uint32_t aBase1 = sb + OFF_A + (uint32_t)((wm*32 + 16 + (lane&15))*512);
    const uint32_t aSwz   = (uint32_t)(((lane&7)) << 4);   // (wm*32+l&15)&7 == lane&7
    const uint32_t hBase0 = sb + OFF_H1 + (uint32_t)((wm*32 +  0 + (lane&15))*256);
    const uint32_t hBase1 = sb + OFF_H1 + (uint32_t)((wm*32 + 16 + (lane&15))*256);
    const uint32_t kSel   = (uint32_t)((lane>>4)*16);
    const uint32_t wSel   = (uint32_t)(((lane>>3)&1)*16);
    uint32_t bRow1[2], bRow2[4];
    #pragma unroll
    for (int e = 0; e < 2; ++e){
        int row = wn*32 + (2*e + (lane>>4))*8 + (lane&7);
        bRow1[e] = (uint32_t)(row*128);
    }
    #pragma unroll
    for (int e = 0; e < 4; ++e){
        int row = wn*64 + (2*e + (lane>>4))*8 + (lane&7);
        bRow2[e] = (uint32_t)(row*128);
    }
    const uint32_t bSwz = (uint32_t)((lane&7)<<4);

    // epilogue1 hoisted addressing: m&7 == g&7
    const uint32_t epSwz = (uint32_t)((g&7)<<4);
    uint32_t colSw1[4];
    #pragma unroll
    for (int nt = 0; nt < 4; ++nt)
        colSw1[nt] = ((uint32_t)(2*(wn*32 + nt*8 + 2*tg))) ^ epSwz;
    uint32_t mBaseH[2][2];
    #pragma unroll
    for (int mt = 0; mt < 2; ++mt)
        #pragma unroll
        for (int half = 0; half < 2; ++half)
            mBaseH[mt][half] = (uint32_t)((wm*32 + mt*16 + g + half*8)*256);

    float d2[2][8][4];
    #pragma unroll
    for (int a=0;a<2;++a)
        #pragma unroll
        for (int bb=0;bb<8;++bb)
            #pragma unroll
            for (int c=0;c<4;++c) d2[a][bb][c] = 0.0f;

    int phE1[2] = {0,0};

    for (int nc = 0; nc < 8; ++nc){
        float b1v[4][2];
        #pragma unroll
        for (int nt = 0; nt < 4; ++nt){
            int ncol = wn*32 + nt*8 + 2*tg;
            b1v[nt][0] = __ldg(b1 + nc*128 + ncol);
            b1v[nt][1] = __ldg(b1 + nc*128 + ncol + 1);
        }

        float c1[2][4][4];
        #pragma unroll
        for (int a=0;a<2;++a)
            #pragma unroll
            for (int bb=0;bb<4;++bb)
                #pragma unroll
                for (int c=0;c<4;++c) c1[a][bb][c] = 0.0f;

        // ---- GEMM1: 4 stages of W1 (16KB each), ring-2 -------------------
        #pragma unroll 1
        for (int kt = 0; kt < 4; ++kt){
            const int s = nc*4 + kt, buf = s & 1;
            MBAR_WAIT(FW1(buf), (s>>1)&1);
            const uint32_t wb = W1BUF(buf);
            const uint32_t aKt = (uint32_t)(kt*128);
            #pragma unroll
            for (int k4 = 0; k4 < 4; ++k4){
                const uint32_t kbW = ((uint32_t)(k4*32) + wSel) ^ bSwz;
                const uint32_t kbA = aKt + (((uint32_t)(k4*32) + kSel) ^ aSwz);
                uint32_t Bf[8];
                ldsm4(Bf,     wb + bRow1[0] + kbW);
                ldsm4(Bf + 4, wb + bRow1[1] + kbW);
                uint32_t A0[4], A1[4];
                ldsm4(A0, aBase0 + kbA);
                ldsm4(A1, aBase1 + kbA);
                #pragma unroll
                for (int nt = 0; nt < 4; ++nt) mma_f16(c1[0][nt], A0, Bf + 2*nt);
                #pragma unroll
                for (int nt = 0; nt < 4; ++nt) mma_f16(c1[1][nt], A1, Bf + 2*nt);
            }
            if (lane == 0) MBAR_ARRIVE(EW1(buf));
            if (tid == 0){
                int s2 = s + 2;
                if (s2 < 32){
                    MBAR_WAIT(EW1(buf), phE1[buf]); phE1[buf] ^= 1;
                    MBAR_EXPECT(FW1(buf), 16384u);
                    bulk_g2s(W1BUF(buf), g_w1 + (size_t)s2*16384u, 16384u, FW1(buf));
                }
            }
        }

        // ---- epilogue1: bias + gelu -> fp16 -> H1 ------------------------
        #pragma unroll
        for (int mt = 0; mt < 2; ++mt){
            #pragma unroll
            for (int nt = 0; nt < 4; ++nt){
                #pragma unroll
                for (int half = 0; half < 2; ++half){
                    float f0 = gelu_exact(c1[mt][nt][half*2+0] + b1v[nt][0]);
                    float f1 = gelu_exact(c1[mt][nt][half*2+1] + b1v[nt][1]);
                    __half2 hp = __floats2half2_rn(f0, f1);
                    *(__half2*)(smp + OFF_H1 + mBaseH[mt][half] + colSw1[nt]) = hp;
                }
            }
        }
        BARH(1 + wm);   // H1 writes visible within wm-group (128 threads)

        // ---- GEMM2: 2 stages of W2 (32KB), single buffer -----------------
        #pragma unroll 1
        for (int kt2 = 0; kt2 < 2; ++kt2){
            const int q = nc*2 + kt2;
            MBAR_WAIT(FW2_, q & 1);
            const uint32_t wb = W2BUF_;
            const uint32_t hKt = (uint32_t)(kt2*128);
            #pragma unroll
            for (int k4 = 0; k4 < 4; ++k4){
                const uint32_t kbW = ((uint32_t)(k4*32) + wSel) ^ bSwz;
                const uint32_t kbH = hKt + (((uint32_t)(k4*32) + kSel) ^ aSwz);
                uint32_t Bf[16];
                #pragma unroll
                for (int e = 0; e < 4; ++e)
                    ldsm4(Bf + 4*e, wb + bRow2[e] + kbW);
                uint32_t H0[4], H1r[4];
                ldsm4(H0,  hBase0 + kbH);
                ldsm4(H1r, hBase1 + kbH);
                #pragma unroll
                for (int nt = 0; nt < 8; ++nt) mma_f16(d2[0][nt], H0,  Bf + 2*nt);
                #pragma unroll
                for (int nt = 0; nt < 8; ++nt) mma_f16(d2[1][nt], H1r, Bf + 2*nt);
            }
            if (lane == 0) MBAR_ARRIVE(EW2_);
            if (tid == 0){
                int q2 = q + 1;
                if (q2 < 16){
                    MBAR_WAIT(EW2_, q & 1);
                    MBAR_EXPECT(FW2_, 32768u);
                    bulk_g2s(W2BUF_, g_w2 + (size_t)q2*32768u, 32768u, FW2_);
                }
            }
        }
        BARH(1 + wm);   // H1 consumed before next chunk overwrites
    }

    // ---- final epilogue: out = s + gate * (D2 + b2) ----------------------
    #pragma unroll
    for (int mt = 0; mt < 2; ++mt){
        #pragma unroll
        for (int half = 0; half < 2; ++half){
            const int m = wm*32 + mt*16 + g + half*8;
            const int t = t0 + m;
            const int idv = idxs[m];
            int rel = ii - (j0 + m);
            rel = rel < -64 ? -64 : (rel > 63 ? 63 : rel);
            rel += 64;
            const float* er = emb + (idv << 8);
            const float* pr = pos + (rel << 8);
            #pragma unroll
            for (int nt = 0; nt < 8; ++nt){
                const int c = wn*64 + nt*8 + 2*tg;
                float2 e2 = *(const float2*)(er + c);
                float2 p2 = *(const float2*)(pr + c);
                float2 sh2 = *(const float2*)(&g_mod[b][c]);
                float2 sc2 = *(const float2*)(&g_mod[b][C_ + c]);
                float2 gt2 = *(const float2*)(&g_mod[b][2*C_ + c]);
                float2 b22 = *(const float2*)(b2 + c);
                float s0 = fmaf(e2.x + p2.x, 1.0f + sc2.x, sh2.x);
                float s1 = fmaf(e2.y + p2.y, 1.0f + sc2.y, sh2.y);
                float2 o;
                o.x = fmaf(gt2.x, d2[mt][nt][half*2+0] + b22.x, s0);
                o.y = fmaf(gt2.y, d2[mt][nt][half*2+1] + b22.y, s1);
                *(float2*)(out + (size_t)t*256 + c) = o;
            }
        }
    }
    __syncthreads();
    if (tid == 0){
        MBAR_INVAL(FW1(0)); MBAR_INVAL(FW1(1));
        MBAR_INVAL(EW1(0)); MBAR_INVAL(EW1(1));
        MBAR_INVAL(FW2_);   MBAR_INVAL(EW2_);
    }
}

// ---------------------------------------------------------------------------
extern "C" void kernel_launch(void* const* d_in, const int* in_sizes, int n_in,
                              void* d_out, int out_size) {
    const float* x     = (const float*)d_in[0];
    const float* c_BD  = (const float*)d_in[1];
    const float* emb   = (const float*)d_in[2];
    const float* pos   = (const float*)d_in[3];
    const float* bins  = (const float*)d_in[4];
    const float* ada_w = (const float*)d_in[5];
    const float* ada_b = (const float*)d_in[6];
    const float* ln_g  = (const float*)d_in[7];
    const float* ln_b  = (const float*)d_in[8];
    const float* fc1_w = (const float*)d_in[9];
    const float* fc1_b = (const float*)d_in[10];
    const float* fc2_w = (const float*)d_in[11];
    const float* fc2_b = (const float*)d_in[12];
    float* out = (float*)d_out;

    static bool attr_set = false;
    if (!attr_set){
        cudaFuncSetAttribute(main_kernel,
                             cudaFuncAttributeMaxDynamicSharedMemorySize, SMEM_BYTES);
        attr_set = true;
    }

    prep_w1<<<1024, 256>>>(fc1_w);
    prep_w2<<<256, 256>>>(fc2_w);
    mod_kernel<<<24, 256>>>(c_BD, ada_w, ada_b);
    main_kernel<<<NTOK/TM, 256, SMEM_BYTES>>>(x, bins, emb, pos, ln_g, ln_b,
                                              fc1_b, fc2_b, out);
}

// round 17
// speedup vs baseline: 1.0591x; 1.0591x over previous
#include <cuda_runtime.h>
#include <cuda_fp16.h>
#include <math.h>
#include <stdint.h>

// Problem constants
#define B_  2
#define L_  256
#define C_  256
#define NTOK (B_*L_*L_)
#define LN_EPS 1e-5f
#define TM 128           // tokens per CTA

// ---------------------------------------------------------------------------
// Device scratch (no cudaMalloc allowed)
__device__ __align__(16) float g_mod[B_][3*C_];
// W1 fp16, SW128: stage s=nc*4+kt -> 16KB [128n x 64k]
__device__ __align__(16) unsigned char g_w1[524288];
// W2 fp16, SW128: stage s=nc*2+kt -> 32KB [256c x 64k]
__device__ __align__(16) unsigned char g_w2[524288];
// H1 fp16 inter-pass buffer: [bt(1024)][nc(8)] x 32KB swizzled tiles
__device__ __align__(256) unsigned char g_h1[268435456];

#define SWZ(o) ((o) ^ (((o)>>3)&0x70))

// ---------------------------------------------------------------------------
__device__ __forceinline__ uint32_t smem_u32(const void* p){
    uint32_t a;
    asm("{ .reg .u64 t; cvta.to.shared.u64 t, %1; cvt.u32.u64 %0, t; }"
        : "=r"(a) : "l"(p));
    return a;
}
#define MBAR_INIT(a,c) \
    asm volatile("mbarrier.init.shared.b64 [%0], %1;" :: "r"(a), "r"(c) : "memory")
#define MBAR_INVAL(a) \
    asm volatile("mbarrier.inval.shared.b64 [%0];" :: "r"(a) : "memory")
#define MBAR_EXPECT(a,tx) \
    asm volatile("mbarrier.arrive.expect_tx.shared.b64 _, [%0], %1;" :: "r"(a), "r"(tx) : "memory")
#define MBAR_ARRIVE(a) \
    asm volatile("mbarrier.arrive.shared.b64 _, [%0];" :: "r"(a) : "memory")
#define MBAR_WAIT(mb, ph) do{                                                   \
    uint32_t _m=(mb), _p=(ph), _d;                                              \
    asm volatile("{\n\t.reg .pred p;\n\t"                                       \
      "mbarrier.try_wait.parity.acquire.cta.shared::cta.b64 p, [%1], %2;\n\t"   \
      "selp.b32 %0,1,0,p;\n\t}" : "=r"(_d) : "r"(_m), "r"(_p) : "memory");      \
    while(!_d){                                                                 \
      asm volatile("{\n\t.reg .pred p;\n\t"                                     \
        "mbarrier.try_wait.parity.acquire.cta.shared::cta.b64 p, [%1], %2, 0x989680;\n\t" \
        "selp.b32 %0,1,0,p;\n\t}" : "=r"(_d) : "r"(_m), "r"(_p) : "memory"); }  \
}while(0)

__device__ __forceinline__ void bulk_g2s(uint32_t dst, const void* src,
                                         uint32_t bytes, uint32_t mbar){
    asm volatile("cp.async.bulk.shared::cluster.global.mbarrier::complete_tx::bytes "
                 "[%0], [%1], %2, [%3];"
                 :: "r"(dst), "l"(src), "r"(bytes), "r"(mbar) : "memory");
}

__device__ __forceinline__ void ldsm4(uint32_t* r, uint32_t a){
    asm volatile("ldmatrix.sync.aligned.m8n8.x4.shared.b16 {%0,%1,%2,%3}, [%4];"
        : "=r"(r[0]),"=r"(r[1]),"=r"(r[2]),"=r"(r[3]) : "r"(a));
}
__device__ __forceinline__ void mma_f16(float* c, const uint32_t* a, const uint32_t* b){
    asm volatile("mma.sync.aligned.m16n8k16.row.col.f32.f16.f16.f32 "
        "{%0,%1,%2,%3}, {%4,%5,%6,%7}, {%8,%9}, {%0,%1,%2,%3};"
        : "+f"(c[0]),"+f"(c[1]),"+f"(c[2]),"+f"(c[3])
        : "r"(a[0]),"r"(a[1]),"r"(a[2]),"r"(a[3]), "r"(b[0]),"r"(b[1]));
}

__device__ __forceinline__ float gelu_exact(float x){
    return 0.5f * x * (1.0f + erff(x * 0.70710678118654752440f));
}

// ---------------------------------------------------------------------------
// Weight prep: fp32 -> fp16, SW128 K-major tiles
__global__ void prep_w1(const float* __restrict__ w1){
    int n = blockIdx.x;            // 0..1023
    int k = threadIdx.x;           // 0..255
    float v = w1[n*256 + k];
    __half h = __float2half_rn(v);
    int nc = n >> 7, nl = n & 127, kt = k >> 6, kk = k & 63;
    size_t tbase = (size_t)(nc*4 + kt) * 16384u;
    uint32_t off = SWZ((uint32_t)(nl*128 + kk*2));
    *(__half*)(g_w1 + tbase + off) = h;
}
__global__ void prep_w2(const float* __restrict__ w2){
    int c = blockIdx.x;            // 0..255
    #pragma unroll
    for (int q = 0; q < 4; ++q){
        int k = threadIdx.x + q*256;   // 0..1023
        float v = w2[c*1024 + k];
        __half h = __float2half_rn(v);
        int nc = k >> 7, kt = (k >> 6) & 1, kk = k & 63;
        size_t tbase = (size_t)(nc*2 + kt) * 32768u;
        uint32_t off = SWZ((uint32_t)(c*128 + kk*2));
        *(__half*)(g_w2 + tbase + off) = h;
    }
}

// ---------------------------------------------------------------------------
// adaLN modulation
__global__ void mod_kernel(const float* __restrict__ c_BD,
                           const float* __restrict__ ada_w,
                           const float* __restrict__ ada_b){
    __shared__ float sc[C_];
    int b   = blockIdx.x / 12;
    int grp = blockIdx.x % 12;
    int tid = threadIdx.x;
    float cv = c_BD[b*C_ + tid];
    sc[tid] = cv / (1.0f + expf(-cv));
    __syncthreads();
    int oo = grp*64 + (tid >> 2);
    int k0 = (tid & 3) * 64;
    const float* wr = ada_w + oo*C_ + k0;
    const float* ss = sc + k0;
    float s = 0.0f;
    #pragma unroll 8
    for (int k = 0; k < 64; ++k) s = fmaf(ss[k], wr[k], s);
    s += __shfl_xor_sync(0xffffffffu, s, 1);
    s += __shfl_xor_sync(0xffffffffu, s, 2);
    if ((tid & 3) == 0) g_mod[b][oo] = s + ada_b[oo];
}

// ===========================================================================
// PASS 1: LN/modulate -> GEMM1 -> gelu -> g_h1 (no CTA barriers in loop)
// SMEM: A 64KB @0 | W1 ring-8 128KB @65536 | idx @196608 | mbars @197120
#define P1_OFF_A   0u
#define P1_OFF_W1  65536u
#define P1_OFF_IDX 196608u
#define P1_OFF_MB  197120u
#define P1_SMEM    197312u
#define P1_FW1(buf) (sb + P1_OFF_MB +  0u + (uint32_t)(buf)*8u)   // 8 bufs
#define P1_EW1(buf) (sb + P1_OFF_MB + 64u + (uint32_t)(buf)*8u)   // 8 bufs
#define P1_W1BUF(buf) (sb + P1_OFF_W1 + (uint32_t)(buf)*16384u)

__global__ __launch_bounds__(512, 1)
void pass1_kernel(const float* __restrict__ x,
                  const float* __restrict__ bins,
                  const float* __restrict__ emb,
                  const float* __restrict__ pos,
                  const float* __restrict__ lng,
                  const float* __restrict__ lnb,
                  const float* __restrict__ b1){
    extern __shared__ __align__(1024) unsigned char smp[];
    const uint32_t sb = smem_u32(smp);
    const int tid  = threadIdx.x;
    const int warp = tid >> 5;
    const int lane = tid & 31;
    const int g    = lane >> 2;
    const int tg   = lane & 3;
    const int wm   = warp >> 2;       // 4 m-groups x 32 rows
    const int wn   = warp & 3;        // 4 n-groups

    const int t0 = blockIdx.x * TM;
    const int b  = t0 >> 16;
    const int ii = (t0 >> 8) & 255;
    const int j0 = t0 & 255;

    int* idxs = (int*)(smp + P1_OFF_IDX);

    if (tid == 0){
        #pragma unroll
        for (int i = 0; i < 8; ++i){ MBAR_INIT(P1_FW1(i), 1); MBAR_INIT(P1_EW1(i), 16); }
    }
    __syncthreads();
    if (tid == 0){
        #pragma unroll
        for (int i = 0; i < 8; ++i){
            MBAR_EXPECT(P1_FW1(i), 16384u);
            bulk_g2s(P1_W1BUF(i), g_w1 + (size_t)i*16384u, 16384u, P1_FW1(i));
        }
    }

    // distance buckets
    if (tid < TM){
        int j = j0 + tid;
        const float* xi = x + (b*L_ + ii)*3;
        const float* xj = x + (b*L_ + j )*3;
        float d0 = __fadd_rn(xi[0], -xj[0]);
        float d1 = __fadd_rn(xi[1], -xj[1]);
        float d2v = __fadd_rn(xi[2], -xj[2]);
        float d  = __fadd_rn(__fadd_rn(__fmul_rn(d0,d0), __fmul_rn(d1,d1)),
                             __fmul_rn(d2v,d2v));
        int cnt = 0;
        #pragma unroll
        for (int k = 0; k < 63; ++k) cnt += (bins[k] < d) ? 1 : 0;
        idxs[tid] = cnt;
    }
    __syncthreads();

    // ---- Phase 0: s -> modulate -> LN -> fp16 into A ---------------------
    {
        float2 sh2[4], sc2[4], lg2[4], lb2[4];
        #pragma unroll
        for (int q = 0; q < 4; ++q){
            int c0 = 2*lane + 64*q;
            sh2[q] = *(const float2*)(&g_mod[b][c0]);
            sc2[q] = *(const float2*)(&g_mod[b][C_ + c0]);
            lg2[q] = *(const float2*)(lng + c0);
            lb2[q] = *(const float2*)(lnb + c0);
        }
        for (int r = 0; r < 8; ++r){
            int m = warp*8 + r;
            int idv = idxs[m];
            int rel = ii - (j0 + m);
            rel = rel < -64 ? -64 : (rel > 63 ? 63 : rel);
            rel += 64;
            const float2* er = (const float2*)(emb + (idv << 8));
            const float2* pr = (const float2*)(pos + (rel << 8));
            float vx[4], vy[4];
            float sum = 0.0f;
            #pragma unroll
            for (int q = 0; q < 4; ++q){
                int c0 = 2*lane + 64*q;
                float2 e = er[c0 >> 1];
                float2 p = pr[c0 >> 1];
                float a0 = fmaf(e.x + p.x, 1.0f + sc2[q].x, sh2[q].x);
                float a1 = fmaf(e.y + p.y, 1.0f + sc2[q].y, sh2[q].y);
                vx[q] = a0; vy[q] = a1;
                sum += a0 + a1;
            }
            #pragma unroll
            for (int off = 16; off; off >>= 1)
                sum += __shfl_xor_sync(0xffffffffu, sum, off);
            float mu = sum * (1.0f/256.0f);
            float sq = 0.0f;
            #pragma unroll
            for (int q = 0; q < 4; ++q){
                float a0 = vx[q]-mu, a1 = vy[q]-mu;
                sq = fmaf(a0,a0, fmaf(a1,a1, sq));
            }
            #pragma unroll
            for (int off = 16; off; off >>= 1)
                sq += __shfl_xor_sync(0xffffffffu, sq, off);
            float rstd = rsqrtf(sq * (1.0f/256.0f) + LN_EPS);
            uint32_t arow = (uint32_t)(m*512) + ((uint32_t)(4*lane) ^ (uint32_t)((m&7)<<4));
            #pragma unroll
            for (int q = 0; q < 4; ++q){
                float h0 = fmaf((vx[q]-mu)*rstd, lg2[q].x, lb2[q].x);
                float h1 = fmaf((vy[q]-mu)*rstd, lg2[q].y, lb2[q].y);
                __half2 hp = __floats2half2_rn(h0, h1);
                *(__half2*)(smp + P1_OFF_A + arow + 128u*q) = hp;
            }
        }
    }
    __syncthreads();

    // per-warp LDSM bases
    const uint32_t aBase0 = sb + P1_OFF_A + (uint32_t)((wm*32 +  0 + (lane&15))*512);
    const uint32_t aBase1 = sb + P1_OFF_A + (uint32_t)((wm*32 + 16 + (lane&15))*512);
    const uint32_t aSwz   = (uint32_t)(((wm*32 + (lane&15)) & 7) << 4);
    const uint32_t kSel   = (uint32_t)((lane>>4)*16);
    const uint32_t wSel   = (uint32_t)(((lane>>3)&1)*16);
    uint32_t bRow1[2];
    #pragma unroll
    for (int e = 0; e < 2; ++e){
        int row = wn*32 + (2*e + (lane>>4))*8 + (lane&7);
        bRow1[e] = (uint32_t)(row*128);
    }
    const uint32_t bSwz = (uint32_t)((lane&7)<<4);

    // H1 store addressing: m&7 == g&7
    const uint32_t epSwz = (uint32_t)((g&7)<<4);
    uint32_t colSw1[4];
    #pragma unroll
    for (int nt = 0; nt < 4; ++nt)
        colSw1[nt] = ((uint32_t)(2*(wn*32 + nt*8 + 2*tg))) ^ epSwz;
    uint32_t mBaseH[2][2];
    #pragma unroll
    for (int mt = 0; mt < 2; ++mt)
        #pragma unroll
        for (int half = 0; half < 2; ++half)
            mBaseH[mt][half] = (uint32_t)((wm*32 + mt*16 + g + half*8)*256);

    int phE1[8] = {0,0,0,0,0,0,0,0};

    for (int nc = 0; nc < 8; ++nc){
        float b1v[4][2];
        #pragma unroll
        for (int nt = 0; nt < 4; ++nt){
            int ncol = wn*32 + nt*8 + 2*tg;
            b1v[nt][0] = __ldg(b1 + nc*128 + ncol);
            b1v[nt][1] = __ldg(b1 + nc*128 + ncol + 1);
        }

        float c1[2][4][4];
        #pragma unroll
        for (int a=0;a<2;++a)
            #pragma unroll
            for (int bb=0;bb<4;++bb)
                #pragma unroll
                for (int c=0;c<4;++c) c1[a][bb][c] = 0.0f;

        #pragma unroll 1
        for (int kt = 0; kt < 4; ++kt){
            const int s = nc*4 + kt, buf = s & 7;
            MBAR_WAIT(P1_FW1(buf), (s>>3)&1);
            const uint32_t wb = P1_W1BUF(buf);
            const uint32_t aKt = (uint32_t)(kt*128);
            #pragma unroll
            for (int k4 = 0; k4 < 4; ++k4){
                const uint32_t kbW = ((uint32_t)(k4*32) + wSel) ^ bSwz;
                const uint32_t kbA = aKt + (((uint32_t)(k4*32) + kSel) ^ aSwz);
                uint32_t Bf[8];
                ldsm4(Bf,     wb + bRow1[0] + kbW);
                ldsm4(Bf + 4, wb + bRow1[1] + kbW);
                uint32_t A0[4], A1[4];
                ldsm4(A0, aBase0 + kbA);
                ldsm4(A1, aBase1 + kbA);
                #pragma unroll
                for (int nt = 0; nt < 4; ++nt) mma_f16(c1[0][nt], A0, Bf + 2*nt);
                #pragma unroll
                for (int nt = 0; nt < 4; ++nt) mma_f16(c1[1][nt], A1, Bf + 2*nt);
            }
            if (lane == 0) MBAR_ARRIVE(P1_EW1(buf));
            if (tid == 0){
                int s2 = s + 8;
                if (s2 < 32){
                    MBAR_WAIT(P1_EW1(buf), phE1[buf]); phE1[buf] ^= 1;
                    MBAR_EXPECT(P1_FW1(buf), 16384u);
                    bulk_g2s(P1_W1BUF(buf), g_w1 + (size_t)s2*16384u, 16384u, P1_FW1(buf));
                }
            }
        }

        // gelu -> g_h1 (direct STG, swizzled tile layout)
        unsigned char* hb = g_h1 + ((size_t)blockIdx.x*8u + (size_t)nc)*32768u;
        #pragma unroll
        for (int mt = 0; mt < 2; ++mt){
            #pragma unroll
            for (int nt = 0; nt < 4; ++nt){
                #pragma unroll
                for (int half = 0; half < 2; ++half){
                    float f0 = gelu_exact(c1[mt][nt][half*2+0] + b1v[nt][0]);
                    float f1 = gelu_exact(c1[mt][nt][half*2+1] + b1v[nt][1]);
                    __half2 hp = __floats2half2_rn(f0, f1);
                    *(__half2*)(hb + mBaseH[mt][half] + colSw1[nt]) = hp;
                }
            }
        }
    }
    __syncthreads();
    if (tid == 0){
        #pragma unroll
        for (int i = 0; i < 8; ++i){ MBAR_INVAL(P1_FW1(i)); MBAR_INVAL(P1_EW1(i)); }
    }
}

// ===========================================================================
// PASS 2: GEMM2 on streamed H1 + final epilogue (no CTA barriers in loop)
// SMEM: H ring-2 64KB @0 | W2 ring-4 128KB @65536 | idx @196608 | mbars @197120
#define P2_OFF_H   0u
#define P2_OFF_W2  65536u
#define P2_OFF_IDX 196608u
#define P2_OFF_MB  197120u
#define P2_SMEM    197312u
#define P2_FH(buf)  (sb + P2_OFF_MB +  0u + (uint32_t)(buf)*8u)   // 2 bufs
#define P2_EH(buf)  (sb + P2_OFF_MB + 16u + (uint32_t)(buf)*8u)   // 2 bufs
#define P2_FW2(buf) (sb + P2_OFF_MB + 32u + (uint32_t)(buf)*8u)   // 4 bufs
#define P2_EW2(buf) (sb + P2_OFF_MB + 64u + (uint32_t)(buf)*8u)   // 4 bufs
#define P2_HBUF(buf)  (sb + P2_OFF_H  + (uint32_t)(buf)*32768u)
#define P2_W2BUF(buf) (sb + P2_OFF_W2 + (uint32_t)(buf)*32768u)

__global__ __launch_bounds__(512, 1)
void pass2_kernel(const float* __restrict__ x,
                  const float* __restrict__ bins,
                  const float* __restrict__ emb,
                  const float* __restrict__ pos,
                  const float* __restrict__ b2,
                  float* __restrict__ out){
    extern __shared__ __align__(1024) unsigned char smp[];
    const uint32_t sb = smem_u32(smp);
    const int tid  = threadIdx.x;
    const int warp = tid >> 5;
    const int lane = tid & 31;
    const int g    = lane >> 2;
    const int tg   = lane & 3;
    const int wm   = warp >> 2;       // 4 m-groups x 32 rows
    const int wn   = warp & 3;        // 4 n-groups

    const int t0 = blockIdx.x * TM;
    const int b  = t0 >> 16;
    const int ii = (t0 >> 8) & 255;
    const int j0 = t0 & 255;

    int* idxs = (int*)(smp + P2_OFF_IDX);
    const unsigned char* hsrc = g_h1 + (size_t)blockIdx.x*8u*32768u;

    if (tid == 0){
        #pragma unroll
        for (int i = 0; i < 2; ++i){ MBAR_INIT(P2_FH(i), 1); MBAR_INIT(P2_EH(i), 16); }
        #pragma unroll
        for (int i = 0; i < 4; ++i){ MBAR_INIT(P2_FW2(i), 1); MBAR_INIT(P2_EW2(i), 16); }
    }
    __syncthreads();
    if (tid == 0){
        #pragma unroll
        for (int i = 0; i < 2; ++i){
            MBAR_EXPECT(P2_FH(i), 32768u);
            bulk_g2s(P2_HBUF(i), hsrc + (size_t)i*32768u, 32768u, P2_FH(i));
        }
        #pragma unroll
        for (int i = 0; i < 4; ++i){
            MBAR_EXPECT(P2_FW2(i), 32768u);
            bulk_g2s(P2_W2BUF(i), g_w2 + (size_t)i*32768u, 32768u, P2_FW2(i));
        }
    }

    // distance buckets (needed for final epilogue's s recompute)
    if (tid < TM){
        int j = j0 + tid;
        const float* xi = x + (b*L_ + ii)*3;
        const float* xj = x + (b*L_ + j )*3;
        float d0 = __fadd_rn(xi[0], -xj[0]);
        float d1 = __fadd_rn(xi[1], -xj[1]);
        float d2v = __fadd_rn(xi[2], -xj[2]);
        float d  = __fadd_rn(__fadd_rn(__fmul_rn(d0,d0), __fmul_rn(d1,d1)),
                             __fmul_rn(d2v,d2v));
        int cnt = 0;
        #pragma unroll
        for (int k = 0; k < 63; ++k) cnt += (bins[k] < d) ? 1 : 0;
        idxs[tid] = cnt;
    }
    __syncthreads();

    // per-warp LDSM bases
    const uint32_t hRow0 = (uint32_t)((wm*32 +  0 + (lane&15))*256);
    const uint32_t hRow1 = (uint32_t)((wm*32 + 16 + (lane&15))*256);
    const uint32_t aSwz  = (uint32_t)(((wm*32 + (lane&15)) & 7) << 4);
    const uint32_t kSel  = (uint32_t)((lane>>4)*16);
    const uint32_t wSel  = (uint32_t)(((lane>>3)&1)*16);
    uint32_t bRow2[4];
    #pragma unroll
    for (int e = 0; e < 4; ++e){
        int row = wn*64 + (2*e + (lane>>4))*8 + (lane&7);
        bRow2[e] = (uint32_t)(row*128);
    }
    const uint32_t bSwz = (uint32_t)((lane&7)<<4);

    float d2[2][8][4];
    #pragma unroll
    for (int a=0;a<2;++a)
        #pragma unroll
        for (int bb=0;bb<8;++bb)
            #pragma unroll
            for (int c=0;c<4;++c) d2[a][bb][c] = 0.0f;

    int phEH[2] = {0,0}, phEW2[4] = {0,0,0,0};

    for (int nc = 0; nc < 8; ++nc){
        const int hb = nc & 1;
        MBAR_WAIT(P2_FH(hb), (nc>>1)&1);
        const uint32_t hstage = P2_HBUF(hb);

        #pragma unroll 1
        for (int kt2 = 0; kt2 < 2; ++kt2){
            const int s = nc*2 + kt2, buf = s & 3;
            MBAR_WAIT(P2_FW2(buf), (s>>2)&1);
            const uint32_t wb = P2_W2BUF(buf);
            const uint32_t hKt = (uint32_t)(kt2*128);
            #pragma unroll
            for (int k4 = 0; k4 < 4; ++k4){
                const uint32_t kbW = ((uint32_t)(k4*32) + wSel) ^ bSwz;
                const uint32_t kbH = hKt + (((uint32_t)(k4*32) + kSel) ^ aSwz);
                uint32_t Bf[16];
                #pragma unroll
                for (int e = 0; e < 4; ++e)
                    ldsm4(Bf + 4*e, wb + bRow2[e] + kbW);
                uint32_t H0[4], H1r[4];
                ldsm4(H0,  hstage + hRow0 + kbH);
                ldsm4(H1r, hstage + hRow1 + kbH);
                #pragma unroll
                for (int nt = 0; nt < 8; ++nt) mma_f16(d2[0][nt], H0,  Bf + 2*nt);
                #pragma unroll
                for (int nt = 0; nt < 8; ++nt) mma_f16(d2[1][nt], H1r, Bf + 2*nt);
            }
            if (lane == 0) MBAR_ARRIVE(P2_EW2(buf));
            if (tid == 0){
                int s2 = s + 4;
                if (s2 < 16){
                    MBAR_WAIT(P2_EW2(buf), phEW2[buf]); phEW2[buf] ^= 1;
                    MBAR_EXPECT(P2_FW2(buf), 32768u);
                    bulk_g2s(P2_W2BUF(buf), g_w2 + (size_t)s2*32768u, 32768u, P2_FW2(buf));
                }
            }
        }
        if (lane == 0) MBAR_ARRIVE(P2_EH(hb));
        if (tid == 0){
            int nc2 = nc + 2;
            if (nc2 < 8){
                MBAR_WAIT(P2_EH(hb), phEH[hb]); phEH[hb] ^= 1;
                MBAR_EXPECT(P2_FH(hb), 32768u);
                bulk_g2s(P2_HBUF(hb), hsrc + (size_t)nc2*32768u, 32768u, P2_FH(hb));
            }
        }
    }

    // ---- final epilogue: out = s + gate * (D2 + b2) ----------------------
    #pragma unroll
    for (int mt = 0; mt < 2; ++mt){
        #pragma unroll
        for (int half = 0; half < 2; ++half){
            const int m = wm*32 + mt*16 + g + half*8;
            const int t = t0 + m;
            const int idv = idxs[m];
            int rel = ii - (j0 + m);
            rel = rel < -64 ? -64 : (rel > 63 ? 63 : rel);
            rel += 64;
            const float* er = emb + (idv << 8);
            const float* pr = pos + (rel << 8);
            #pragma unroll
            for (int nt = 0; nt < 8; ++nt){
                const int c = wn*64 + nt*8 + 2*tg;
                float2 e2 = *(const float2*)(er + c);
                float2 p2 = *(const float2*)(pr + c);
                float2 sh2 = *(const float2*)(&g_mod[b][c]);
                float2 sc2 = *(const float2*)(&g_mod[b][C_ + c]);
                float2 gt2 = *(const float2*)(&g_mod[b][2*C_ + c]);
                float2 b22 = *(const float2*)(b2 + c);
                float s0 = fmaf(e2.x + p2.x, 1.0f + sc2.x, sh2.x);
                float s1 = fmaf(e2.y + p2.y, 1.0f + sc2.y, sh2.y);
                float2 o;
                o.x = fmaf(gt2.x, d2[mt][nt][half*2+0] + b22.x, s0);
                o.y = fmaf(gt2.y, d2[mt][nt][half*2+1] + b22.y, s1);
                *(float2*)(out + (size_t)t*256 + c) = o;
            }
        }
    }
    __syncthreads();
    if (tid == 0){
        #pragma unroll
        for (int i = 0; i < 2; ++i){ MBAR_INVAL(P2_FH(i)); MBAR_INVAL(P2_EH(i)); }
        #pragma unroll
        for (int i = 0; i < 4; ++i){ MBAR_INVAL(P2_FW2(i)); MBAR_INVAL(P2_EW2(i)); }
    }
}

// ---------------------------------------------------------------------------
extern "C" void kernel_launch(void* const* d_in, const int* in_sizes, int n_in,
                              void* d_out, int out_size) {
    const float* x     = (const float*)d_in[0];
    const float* c_BD  = (const float*)d_in[1];
    const float* emb   = (const float*)d_in[2];
    const float* pos   = (const float*)d_in[3];
    const float* bins  = (const float*)d_in[4];
    const float* ada_w = (const float*)d_in[5];
    const float* ada_b = (const float*)d_in[6];
    const float* ln_g  = (const float*)d_in[7];
    const float* ln_b  = (const float*)d_in[8];
    const float* fc1_w = (const float*)d_in[9];
    const float* fc1_b = (const float*)d_in[10];
    const float* fc2_w = (const float*)d_in[11];
    const float* fc2_b = (const float*)d_in[12];
    float* out = (float*)d_out;

    static bool attr_set = false;
    if (!attr_set){
        cudaFuncSetAttribute(pass1_kernel,
                             cudaFuncAttributeMaxDynamicSharedMemorySize, P1_SMEM);
        cudaFuncSetAttribute(pass2_kernel,
                             cudaFuncAttributeMaxDynamicSharedMemorySize, P2_SMEM);
        attr_set = true;
    }

    prep_w1<<<1024, 256>>>(fc1_w);
    prep_w2<<<256, 256>>>(fc2_w);
    mod_kernel<<<24, 256>>>(c_BD, ada_w, ada_b);
    pass1_kernel<<<NTOK/TM, 512, P1_SMEM>>>(x, bins, emb, pos, ln_g, ln_b, fc1_b);
    pass2_kernel<<<NTOK/TM, 512, P2_SMEM>>>(x, bins, emb, pos, fc2_b, out);
}